// round 4
// baseline (speedup 1.0000x reference)
#include <cuda_runtime.h>
#include <cuda_fp16.h>

#define NN 100000
#define EE 3200000
#define GG 1024
#define DD 32
#define TILE 1024
#define NTILES ((NN + TILE - 1) / TILE)   // 98

// ---- scratch (static __device__, no allocations) ----
__device__ int    g_deg[NN];
__device__ int    g_off[NN];
__device__ int    g_cur[NN];
__device__ int    g_csr[EE];
__device__ int    g_bsum[128];
__device__ float4 g_x4[NN];
__device__ __half g_h0[NN * DD];   // fp16 feature rows (64B/row)
__device__ __half g_h1[NN * DD];
__device__ float  g_pool[GG * DD];

__device__ __forceinline__ void upk_add(unsigned int u, float& a, float& b) {
    __half2 h = *reinterpret_cast<__half2*>(&u);
    float2 f = __half22float2(h);
    a += f.x; b += f.y;
}

// ---------------- init: zero deg + pool, pad x to float4 ----------------
__global__ void k_init(const float* __restrict__ x) {
    int i = blockIdx.x * blockDim.x + threadIdx.x;
    if (i < NN) {
        g_deg[i] = 0;
        g_x4[i] = make_float4(x[3 * i], x[3 * i + 1], x[3 * i + 2], 0.f);
    }
    if (i < GG * DD) g_pool[i] = 0.f;
}

// ---------------- CSR build ----------------
__global__ void k_hist(const int* __restrict__ ei) {
    int e = (blockIdx.x * blockDim.x + threadIdx.x) * 4;
    if (e < EE) {
        int4 d = *(const int4*)(ei + EE + e);
        atomicAdd(&g_deg[d.x], 1);
        atomicAdd(&g_deg[d.y], 1);
        atomicAdd(&g_deg[d.z], 1);
        atomicAdd(&g_deg[d.w], 1);
    }
}

__global__ void k_scan1() {
    __shared__ int sh[TILE];
    int t = threadIdx.x;
    int idx = blockIdx.x * TILE + t;
    int v = (idx < NN) ? g_deg[idx] : 0;
    sh[t] = v;
    __syncthreads();
    for (int off = 1; off < TILE; off <<= 1) {
        int u = (t >= off) ? sh[t - off] : 0;
        __syncthreads();
        sh[t] += u;
        __syncthreads();
    }
    if (idx < NN) g_off[idx] = sh[t] - v;          // tile-local exclusive
    if (t == TILE - 1) g_bsum[blockIdx.x] = sh[t]; // tile total
}

__global__ void k_scan2() {
    __shared__ int sh[128];
    int t = threadIdx.x;
    int v = (t < NTILES) ? g_bsum[t] : 0;
    sh[t] = v;
    __syncthreads();
    for (int off = 1; off < 128; off <<= 1) {
        int u = (t >= off) ? sh[t - off] : 0;
        __syncthreads();
        sh[t] += u;
        __syncthreads();
    }
    if (t < NTILES) g_bsum[t] = sh[t] - v;         // exclusive tile offsets
}

__global__ void k_scan3() {
    int idx = blockIdx.x * TILE + threadIdx.x;
    if (idx < NN) {
        int o = g_off[idx] + g_bsum[blockIdx.x];
        g_off[idx] = o;
        g_cur[idx] = o;
    }
}

__global__ void k_fill(const int* __restrict__ ei) {
    int e = (blockIdx.x * blockDim.x + threadIdx.x) * 4;
    if (e < EE) {
        int4 s = *(const int4*)(ei + e);
        int4 d = *(const int4*)(ei + EE + e);
        int p0 = atomicAdd(&g_cur[d.x], 1);
        int p1 = atomicAdd(&g_cur[d.y], 1);
        int p2 = atomicAdd(&g_cur[d.z], 1);
        int p3 = atomicAdd(&g_cur[d.w], 1);
        g_csr[p0] = s.x;
        g_csr[p1] = s.y;
        g_csr[p2] = s.z;
        g_csr[p3] = s.w;
    }
}

// ---------------- layer 1 (F_IN=3 -> 32), writes fp16 ----------------
__global__ void k_layer1(const float* __restrict__ Wa, const float* __restrict__ ba,
                         const float* __restrict__ Wb, const float* __restrict__ bb,
                         const float* __restrict__ gm, const float* __restrict__ be,
                         const float* __restrict__ mm, const float* __restrict__ vv) {
    __shared__ float sWa[96], sWb[1024], sba[32], sbb[32], ssc[32], ssh[32];
    int tid = threadIdx.x;
    for (int i = tid; i < 1024; i += blockDim.x) sWb[i] = Wb[i];
    if (tid < 96) sWa[tid] = Wa[tid];
    if (tid < 32) {
        sba[tid] = ba[tid];
        sbb[tid] = bb[tid];
        float sc = gm[tid] * rsqrtf(vv[tid] + 1e-5f);
        ssc[tid] = sc;
        ssh[tid] = be[tid] - mm[tid] * sc;
    }
    __syncthreads();
    int warp = (blockIdx.x * blockDim.x + tid) >> 5;
    int lane = tid & 31;
    if (warp >= NN) return;
    int n = warp;
    int o = g_off[n], d = g_deg[n];
    float p0 = 0.f, p1 = 0.f, p2 = 0.f;
    for (int j = lane; j < d; j += 32) {
        float4 r = g_x4[g_csr[o + j]];
        p0 += r.x; p1 += r.y; p2 += r.z;
    }
#pragma unroll
    for (int w = 16; w > 0; w >>= 1) {
        p0 += __shfl_xor_sync(0xffffffffu, p0, w);
        p1 += __shfl_xor_sync(0xffffffffu, p1, w);
        p2 += __shfl_xor_sync(0xffffffffu, p2, w);
    }
    float4 self = g_x4[n];
    float a0 = p0 + self.x, a1 = p1 + self.y, a2 = p2 + self.z;
    float acc = fmaf(a0, sWa[lane], sba[lane]);
    acc = fmaf(a1, sWa[32 + lane], acc);
    acc = fmaf(a2, sWa[64 + lane], acc);
    acc = fmaxf(acc, 0.f);
    float acc2 = sbb[lane];
#pragma unroll
    for (int k = 0; k < 32; k++) {
        float a = __shfl_sync(0xffffffffu, acc, k);
        acc2 = fmaf(a, sWb[k * 32 + lane], acc2);
    }
    acc2 = fmaxf(acc2, 0.f);
    g_h0[n * 32 + lane] = __float2half_rn(fmaf(acc2, ssc[lane], ssh[lane]));
}

// ---------------- layers 2/3 core: fp16 gather, 8 edges/warp-iter ----------------
// Computes the post-BN fp32 value for feature `lane` of node `n`.
__device__ __forceinline__ float layer32_node(const uint4* __restrict__ hin4, int n, int lane,
                                              const float* sWa, const float* sWb,
                                              const float* sba, const float* sbb,
                                              const float* ssc, const float* ssh) {
    int grp = lane >> 2;   // edge group 0..7
    int chk = lane & 3;    // 16B chunk (8 halves) 0..3
    float a0 = 0.f, a1 = 0.f, a2 = 0.f, a3 = 0.f, a4 = 0.f, a5 = 0.f, a6 = 0.f, a7 = 0.f;
    if (grp == 0) {                       // self term once
        uint4 v = hin4[n * 4 + chk];
        upk_add(v.x, a0, a1); upk_add(v.y, a2, a3);
        upk_add(v.z, a4, a5); upk_add(v.w, a6, a7);
    }
    int o = g_off[n];
    int jend = o + g_deg[n];
#pragma unroll 2
    for (int j = o + grp; j < jend; j += 8) {
        int ss = g_csr[j];                // 8 ints per warp, 4-way broadcast
        uint4 v = hin4[ss * 4 + chk];     // 8 distinct 64B rows per warp-iter
        upk_add(v.x, a0, a1); upk_add(v.y, a2, a3);
        upk_add(v.z, a4, a5); upk_add(v.w, a6, a7);
    }
    // reduce across the 8 edge groups (lane bits 2..4)
#pragma unroll
    for (int w = 4; w <= 16; w <<= 1) {
        a0 += __shfl_xor_sync(0xffffffffu, a0, w);
        a1 += __shfl_xor_sync(0xffffffffu, a1, w);
        a2 += __shfl_xor_sync(0xffffffffu, a2, w);
        a3 += __shfl_xor_sync(0xffffffffu, a3, w);
        a4 += __shfl_xor_sync(0xffffffffu, a4, w);
        a5 += __shfl_xor_sync(0xffffffffu, a5, w);
        a6 += __shfl_xor_sync(0xffffffffu, a6, w);
        a7 += __shfl_xor_sync(0xffffffffu, a7, w);
    }
    // feature k: element (k&7) of lanes with chk == k>>3 -> src lane k>>3
    float acc = sba[lane];
#pragma unroll
    for (int k = 0; k < 32; k++) {
        float comp = ((k & 7) == 0) ? a0 : ((k & 7) == 1) ? a1 :
                     ((k & 7) == 2) ? a2 : ((k & 7) == 3) ? a3 :
                     ((k & 7) == 4) ? a4 : ((k & 7) == 5) ? a5 :
                     ((k & 7) == 6) ? a6 : a7;
        float a = __shfl_sync(0xffffffffu, comp, k >> 3);
        acc = fmaf(a, sWa[k * 32 + lane], acc);
    }
    acc = fmaxf(acc, 0.f);
    float acc2 = sbb[lane];
#pragma unroll
    for (int k = 0; k < 32; k++) {
        float a = __shfl_sync(0xffffffffu, acc, k);
        acc2 = fmaf(a, sWb[k * 32 + lane], acc2);
    }
    acc2 = fmaxf(acc2, 0.f);
    return fmaf(acc2, ssc[lane], ssh[lane]);
}

#define LOAD_MLP_SMEM()                                              \
    __shared__ float sWa[1024], sWb[1024], sba[32], sbb[32], ssc[32], ssh[32]; \
    {                                                                \
        int t = threadIdx.x;                                         \
        for (int i = t; i < 1024; i += blockDim.x) {                 \
            sWa[i] = Wa[i];                                          \
            sWb[i] = Wb[i];                                          \
        }                                                            \
        if (t < 32) {                                                \
            sba[t] = ba[t];                                          \
            sbb[t] = bb[t];                                          \
            float sc = gm[t] * rsqrtf(vv[t] + 1e-5f);                \
            ssc[t] = sc;                                             \
            ssh[t] = be[t] - mm[t] * sc;                             \
        }                                                            \
        __syncthreads();                                             \
    }

// layer 2: g_h0 -> g_h1 (fp16 out)
__global__ void k_layer2(const float* __restrict__ Wa, const float* __restrict__ ba,
                         const float* __restrict__ Wb, const float* __restrict__ bb,
                         const float* __restrict__ gm, const float* __restrict__ be,
                         const float* __restrict__ mm, const float* __restrict__ vv) {
    LOAD_MLP_SMEM();
    int warp = (blockIdx.x * blockDim.x + threadIdx.x) >> 5;
    int lane = threadIdx.x & 31;
    if (warp >= NN) return;
    float r = layer32_node((const uint4*)g_h0, warp, lane, sWa, sWb, sba, sbb, ssc, ssh);
    g_h1[warp * 32 + lane] = __float2half_rn(r);
}

// layer 3: g_h1 -> pool (fp32 atomics, fused global_add_pool)
__global__ void k_layer3(const int* __restrict__ batch,
                         const float* __restrict__ Wa, const float* __restrict__ ba,
                         const float* __restrict__ Wb, const float* __restrict__ bb,
                         const float* __restrict__ gm, const float* __restrict__ be,
                         const float* __restrict__ mm, const float* __restrict__ vv) {
    LOAD_MLP_SMEM();
    int warp = (blockIdx.x * blockDim.x + threadIdx.x) >> 5;
    int lane = threadIdx.x & 31;
    if (warp >= NN) return;
    float r = layer32_node((const uint4*)g_h1, warp, lane, sWa, sWb, sba, sbb, ssc, ssh);
    atomicAdd(&g_pool[batch[warp] * 32 + lane], r);
}

// ---------------- head MLP ----------------
__global__ void k_final(const float* __restrict__ Wf1, const float* __restrict__ bf1,
                        const float* __restrict__ Wf2, const float* __restrict__ bf2,
                        float* __restrict__ out) {
    __shared__ float sW1[1024], sb1[32], sW2[32];
    int tid = threadIdx.x;
    for (int i = tid; i < 1024; i += blockDim.x) sW1[i] = Wf1[i];
    if (tid < 32) {
        sb1[tid] = bf1[tid];
        sW2[tid] = Wf2[tid];
    }
    __syncthreads();
    int warp = (blockIdx.x * blockDim.x + tid) >> 5;
    int lane = tid & 31;
    if (warp >= GG) return;
    float p = g_pool[warp * 32 + lane];
    float acc = sb1[lane];
#pragma unroll
    for (int k = 0; k < 32; k++) {
        float a = __shfl_sync(0xffffffffu, p, k);
        acc = fmaf(a, sW1[k * 32 + lane], acc);
    }
    acc = fmaxf(acc, 0.f);
    float part = acc * sW2[lane];
#pragma unroll
    for (int w = 16; w > 0; w >>= 1) part += __shfl_xor_sync(0xffffffffu, part, w);
    if (lane == 0) out[warp] = tanhf(part + bf2[0]);
}

extern "C" void kernel_launch(void* const* d_in, const int* in_sizes, int n_in,
                              void* d_out, int out_size) {
    const float* x = (const float*)d_in[0];
    const int* ei = (const int*)d_in[1];
    const int* batch = (const int*)d_in[2];
    const float* P[28];
    for (int i = 0; i < 28; i++) P[i] = (const float*)d_in[3 + i];
    float* out = (float*)d_out;

    const int TB = 256;
    // init + CSR build (by dst)
    k_init<<<(NN + TB - 1) / TB, TB>>>(x);
    k_hist<<<(EE / 4 + TB - 1) / TB, TB>>>(ei);
    k_scan1<<<NTILES, TILE>>>();
    k_scan2<<<1, 128>>>();
    k_scan3<<<NTILES, TILE>>>();
    k_fill<<<(EE / 4 + TB - 1) / TB, TB>>>(ei);

    int node_grid = (NN * 32 + TB - 1) / TB;   // warp per node
    k_layer1<<<node_grid, TB>>>(P[0], P[1], P[2], P[3], P[4], P[5], P[6], P[7]);
    k_layer2<<<node_grid, TB>>>(P[8], P[9], P[10], P[11], P[12], P[13], P[14], P[15]);
    k_layer3<<<node_grid, TB>>>(batch, P[16], P[17], P[18], P[19], P[20], P[21], P[22], P[23]);

    k_final<<<(GG * DD + TB - 1) / TB, TB>>>(P[24], P[25], P[26], P[27], out);
}